// round 12
// baseline (speedup 1.0000x reference)
#include <cuda_runtime.h>
#include <cuda_fp16.h>
#include <math.h>
#include <stdint.h>

// Problem constants
#define BB    64
#define NN    512
#define MROWS (BB*NN)        // 32768 nodes
#define DEG   8
#define ETOT  (MROWS*DEG)    // 262144 edges
#define EB    (NN*DEG)       // 4096 edges per batch
#define HD    512            // D == H == 512
#define CC    16
#define VOCAB 10000
#define MAXD  64             // max in-degree capacity (Poisson(8); P(>=64) ~ 1e-40)
#define BN_EPS 1e-5f

// fp8 scaling: activations x8, weights x16 -> accumulator descale 1/128
#define SACT   8.0f
#define SWGT   16.0f
#define ISCALE (1.0f / 128.0f)

// ---------------- static scratch ----------------
__device__ __align__(1024) __half  g_E16[VOCAB*HD];         // emb fp16
__device__ __align__(1024) uint8_t g_A8[MROWS*HD];          // z0 e4m3 (x8)
__device__ __align__(1024) uint8_t g_B8[MROWS*HD];          // z1 e4m3 (x8)
__device__ __align__(1024) uint8_t g_W1q[HD*HD];            // [n][k] e4m3 (x16)
__device__ __align__(1024) uint8_t g_W2q[HD*HD];
__device__ __align__(1024) float   g_logits[MROWS*CC];      // pre-softmax pool logits
__device__ int   g_deg[MROWS];                              // out-degree (adj.sum(-1))
__device__ int   g_cnt[MROWS];                              // in-degree cursor
__device__ int   g_slots[MROWS*MAXD];                       // src lists per dst (8 MB)

__device__ __forceinline__ float warpSum(float v) {
    #pragma unroll
    for (int o = 16; o; o >>= 1) v += __shfl_xor_sync(0xffffffffu, v, o);
    return v;
}

// ---------------- PTX helpers ----------------
__device__ __forceinline__ uint32_t smem_u32(const void* p) {
    uint32_t a;
    asm("{ .reg .u64 t; cvta.to.shared.u64 t, %1; cvt.u32.u64 %0, t; }" : "=r"(a) : "l"(p));
    return a;
}
__device__ __forceinline__ void cp16(uint32_t dst, const void* src) {
    asm volatile("cp.async.cg.shared.global [%0], [%1], 16;\n" :: "r"(dst), "l"(src));
}
__device__ __forceinline__ void cp_commit() {
    asm volatile("cp.async.commit_group;\n" ::: "memory");
}
template<int N>
__device__ __forceinline__ void cp_wait() {
    asm volatile("cp.async.wait_group %0;\n" :: "n"(N) : "memory");
}
__device__ __forceinline__ void ldm_x4(uint32_t* r, uint32_t addr) {
    asm volatile("ldmatrix.sync.aligned.m8n8.x4.shared.b16 {%0,%1,%2,%3}, [%4];"
                 : "=r"(r[0]), "=r"(r[1]), "=r"(r[2]), "=r"(r[3]) : "r"(addr));
}
// fp8 e4m3 MMA: m16n8k32, fragment bytes identical to fp16 m16n8k16 ldmatrix pattern
__device__ __forceinline__ void mma16832q(float* d, const uint32_t* a, const uint32_t* b) {
    asm volatile("mma.sync.aligned.m16n8k32.row.col.f32.e4m3.e4m3.f32 "
                 "{%0,%1,%2,%3}, {%4,%5,%6,%7}, {%8,%9}, {%0,%1,%2,%3};"
                 : "+f"(d[0]), "+f"(d[1]), "+f"(d[2]), "+f"(d[3])
                 : "r"(a[0]), "r"(a[1]), "r"(a[2]), "r"(a[3]), "r"(b[0]), "r"(b[1]));
}
// pack two floats -> e4m3x2 (lo -> low byte, hi -> high byte)
__device__ __forceinline__ uint16_t fp8x2(float lo, float hi) {
    uint16_t r;
    asm("cvt.rn.satfinite.e4m3x2.f32 %0, %1, %2;" : "=h"(r) : "f"(hi), "f"(lo));
    return r;
}

// ---------------- prep: init + emb->fp16 + W transpose->e4m3 ----------------
__global__ void prep_kernel(const float* __restrict__ emb,
                            const float* __restrict__ w1, const float* __restrict__ w2,
                            float* out) {
    int i = blockIdx.x * blockDim.x + threadIdx.x;
    if (i < MROWS) {
        g_cnt[i] = 0; g_deg[i] = 0;
        float4 z = make_float4(0.f, 0.f, 0.f, 0.f);
        float4* lg = (float4*)(g_logits + i * CC);
        lg[0] = z; lg[1] = z; lg[2] = z; lg[3] = z;
    }
    if (i < VOCAB * HD / 2) {
        float2 v = ((const float2*)emb)[i];
        ((__half2*)g_E16)[i] = __floats2half2_rn(v.x, v.y);
    }
    if (i < HD * HD) {       // i = k*512 + n
        int k = i >> 9, n = i & 511;
        g_W1q[n * HD + k] = (uint8_t)(fp8x2(w1[i] * SWGT, 0.f) & 0xff);
        g_W2q[n * HD + k] = (uint8_t)(fp8x2(w2[i] * SWGT, 0.f) & 0xff);
    }
    if (i == 0) out[0] = 0.f;
}

// ---------------- single-pass edge processing: slots + degrees ----------------
__global__ void edge_kernel(const int* __restrict__ ei) {
    int e = blockIdx.x * blockDim.x + threadIdx.x;
    if (e < ETOT) {
        int s = ei[e];
        int d = ei[ETOT + e];
        int p = atomicAdd(&g_cnt[d], 1);
        if (p < MAXD) g_slots[d * MAXD + p] = s;
        atomicAdd(&g_deg[s], 1);
    }
}

// ---------------- z0 = emb16[x] + segment_sum(...), output e4m3 x8 ----------------
__global__ __launch_bounds__(256) void z0_kernel(const int* __restrict__ x) {
    __shared__ int s_sx[4][MAXD];
    __shared__ int s_meta[4][2];       // [cnt, self_token]
    int t = threadIdx.x;
    int sub = t >> 6, lane = t & 63;
    int n = blockIdx.x * 4 + sub;
    int cnt = min(g_cnt[n], MAXD);
    if (lane == 0) { s_meta[sub][0] = cnt; s_meta[sub][1] = x[n]; }
    if (lane < cnt) s_sx[sub][lane] = x[g_slots[n * MAXD + lane]];
    __syncthreads();

    const uint4* emb4 = (const uint4*)g_E16;   // 8 halves per uint4, 64 per row
    cnt = s_meta[sub][0];
    uint4 hv = emb4[(size_t)s_meta[sub][1] * 64 + lane];
    __half2 a0 = *(__half2*)&hv.x, a1 = *(__half2*)&hv.y;
    __half2 a2 = *(__half2*)&hv.z, a3 = *(__half2*)&hv.w;
    for (int e = 0; e < cnt; e++) {
        uint4 v = emb4[(size_t)s_sx[sub][e] * 64 + lane];
        a0 = __hadd2(a0, *(__half2*)&v.x);
        a1 = __hadd2(a1, *(__half2*)&v.y);
        a2 = __hadd2(a2, *(__half2*)&v.z);
        a3 = __hadd2(a3, *(__half2*)&v.w);
    }
    float2 f0 = __half22float2(a0), f1 = __half22float2(a1);
    float2 f2 = __half22float2(a2), f3 = __half22float2(a3);
    uint32_t p01 = (uint32_t)fp8x2(f0.x * SACT, f0.y * SACT)
                 | ((uint32_t)fp8x2(f1.x * SACT, f1.y * SACT) << 16);
    uint32_t p23 = (uint32_t)fp8x2(f2.x * SACT, f2.y * SACT)
                 | ((uint32_t)fp8x2(f3.x * SACT, f3.y * SACT) << 16);
    uint2 outv; outv.x = p01; outv.y = p23;
    ((uint2*)g_A8)[(size_t)n * 64 + lane] = outv;   // 8 bytes per lane, 512 B/row
}

// ---------------- fp8 mma.sync GEMM ----------------
// 128x128 CTA tile, 8 warps (2x4), warp tile 64x32, K-chunk 128 (bytes=128), 4 chunks,
// 3-stage cp.async, 2 CTAs/SM. Fragment layout identical to fp16 path (b16 ldmatrix).
// WHICH==0: z1 = elu(bn(z0 @ w1 + b1)) -> g_B8 (e4m3 x8)
// WHICH==1: z2 = elu(z1 @ w2 + b2), fused pool: atomicAdd partial z2@pool_w logits

#define STAGE_BYTES 32768          // A 16K | W 16K (128 rows x 128 B)
#define NSTAGE 3
#define SMEM_GEMM (NSTAGE * STAGE_BYTES)   // 96 KB

template<int WHICH>
__global__ __launch_bounds__(256, 2) void gemm_mma(
    const float* __restrict__ bias, const float* __restrict__ gamma,
    const float* __restrict__ beta, const float* __restrict__ mean,
    const float* __restrict__ var, const float* __restrict__ poolw)
{
    extern __shared__ __align__(1024) char smem[];
    const uint32_t sb = smem_u32(smem);
    const int tid = threadIdx.x;
    const int wid = tid >> 5, lane = tid & 31;
    const int wm = wid & 1;        // 0..1 -> 64 rows
    const int wn = wid >> 1;       // 0..3 -> 32 cols
    const int rowBase = blockIdx.y * 128;
    const int colBase = blockIdx.x * 128;

    const uint8_t* __restrict__ Ap = WHICH ? g_B8 : g_A8;
    const uint8_t* __restrict__ Wp = WHICH ? g_W2q : g_W1q;

    // ---- loader: 8 x 16B cp.async per thread per chunk (chunk = 128 K-bytes) ----
    auto loadChunk = [&](int c, int s) {
        const uint32_t stage = sb + s * STAGE_BYTES;
        #pragma unroll
        for (int it = 0; it < 8; it++) {
            int idx = tid + it * 256;
            int q = idx >> 10;                    // 0=A, 1=W
            int r = (idx & 1023) >> 3;
            int cc = idx & 7;
            const uint8_t* base = q ? Wp : Ap;
            int grow = (q ? colBase : rowBase) + r;
            const uint8_t* src = base + (size_t)grow * HD + c * 128 + cc * 16;
            uint32_t off = r * 128 + cc * 16;
            uint32_t sw = off ^ ((off >> 3) & 0x70);
            cp16(stage + q * 16384 + sw, src);
        }
        cp_commit();
    };

    // ---- ldmatrix per-thread addressing (identical to fp16 path) ----
    const int g = lane >> 3;                  // 0..3
    const int aRowL = (g & 1) * 8 + (lane & 7);
    const int aKb   = (g >> 1);
    const int bRowL = (g >> 1) * 8 + (lane & 7);
    const int bKb   = (g & 1);

    uint32_t aRowOff[4], aXor[4];
    #pragma unroll
    for (int i = 0; i < 4; i++) {
        int ar = wm * 64 + i * 16 + aRowL;
        aRowOff[i] = ar * 128;
        aXor[i] = (ar & 7) << 4;
    }
    uint32_t bRowOff[2], bXor[2];
    #pragma unroll
    for (int p = 0; p < 2; p++) {
        int br = wn * 32 + p * 16 + bRowL;
        bRowOff[p] = br * 128;
        bXor[p] = (br & 7) << 4;
    }

    float acc[4][4][4] = {};

    loadChunk(0, 0);
    loadChunk(1, 1);

    for (int c = 0; c < 4; c++) {
        if (c < 3) cp_wait<1>(); else cp_wait<0>();
        __syncthreads();
        if (c + 2 < 4) loadChunk(c + 2, (c + 2) % NSTAGE);

        const uint32_t stage = sb + (c % NSTAGE) * STAGE_BYTES;
        const uint32_t aPl = stage, bPl = stage + 16384;

        #pragma unroll
        for (int s = 0; s < 4; s++) {          // k32 steps within 128-byte chunk
            uint32_t ah[4][4], bh[2][4];
            uint32_t aCol = (uint32_t)(s * 32 + aKb * 16);
            uint32_t bCol = (uint32_t)(s * 32 + bKb * 16);
            #pragma unroll
            for (int i = 0; i < 4; i++)
                ldm_x4(ah[i], aPl + aRowOff[i] + (aCol ^ aXor[i]));
            #pragma unroll
            for (int p = 0; p < 2; p++)
                ldm_x4(bh[p], bPl + bRowOff[p] + (bCol ^ bXor[p]));
            #pragma unroll
            for (int i = 0; i < 4; i++)
                #pragma unroll
                for (int j = 0; j < 4; j++)
                    mma16832q(acc[i][j], ah[i], &bh[j >> 1][(j & 1) * 2]);
        }
    }
    __syncthreads();   // protect epilogue smem reuse against last chunk reads

    // ---- epilogue ----
    const int rlane = lane >> 2;
    const int clane = (lane & 3) * 2;
    float* sE = (float*)smem;                 // [128][129] for WHICH==1

    #pragma unroll
    for (int i = 0; i < 4; i++) {
        int rl0 = wm * 64 + i * 16 + rlane;
        #pragma unroll
        for (int j = 0; j < 4; j++) {
            int cl = wn * 32 + j * 8 + clane;
            int col = colBase + cl;
            float b0 = bias[col], b1v = bias[col + 1];
            float s0 = 1.f, s1 = 1.f, o0 = 0.f, o1 = 0.f;
            if (WHICH == 0) {
                s0 = rsqrtf(var[col] + BN_EPS) * gamma[col];
                s1 = rsqrtf(var[col + 1] + BN_EPS) * gamma[col + 1];
                o0 = beta[col] - mean[col] * s0;
                o1 = beta[col + 1] - mean[col + 1] * s1;
            }
            #pragma unroll
            for (int h = 0; h < 2; h++) {
                int rl = rl0 + h * 8;
                float v0 = acc[i][j][h * 2 + 0] * ISCALE + b0;
                float v1 = acc[i][j][h * 2 + 1] * ISCALE + b1v;
                if (WHICH == 0) { v0 = v0 * s0 + o0; v1 = v1 * s1 + o1; }
                v0 = v0 > 0.f ? v0 : expm1f(v0);
                v1 = v1 > 0.f ? v1 : expm1f(v1);
                if (WHICH == 0) {
                    *(uint16_t*)(g_B8 + (size_t)(rowBase + rl) * HD + col) =
                        fp8x2(v0 * SACT, v1 * SACT);
                } else {
                    sE[rl * 129 + cl] = v0;
                    sE[rl * 129 + cl + 1] = v1;
                }
            }
        }
    }

    if (WHICH == 1) {
        // fused pool: partial logits = sE(128x128) @ pool_w[colBase:colBase+128, 0:16]
        float* sPw = sE + 128 * 129;          // [128][16] = 8 KB
        __syncthreads();
        #pragma unroll
        for (int jj = 0; jj < 8; jj++) {
            int idx = tid * 8 + jj;
            int k = idx >> 4, cch = idx & 15;
            sPw[k * 16 + cch] = poolw[(size_t)(colBase + k) * CC + cch];
        }
        __syncthreads();
        int r = tid & 127;
        int c0 = (tid >> 7) * 8;
        float a8[8] = {};
        #pragma unroll 4
        for (int k = 0; k < 128; k++) {
            float zv = sE[r * 129 + k];
            #pragma unroll
            for (int c8 = 0; c8 < 8; c8++) a8[c8] += zv * sPw[k * 16 + c0 + c8];
        }
        float* dst = g_logits + (size_t)(rowBase + r) * CC + c0;
        #pragma unroll
        for (int c8 = 0; c8 < 8; c8++) atomicAdd(dst + c8, a8[c8]);
    }
}

// ---------------- per-batch losses (softmax fused in) ----------------
__global__ __launch_bounds__(256) void loss_kernel(const int* __restrict__ ei,
                                                   const float* __restrict__ pb,
                                                   float* __restrict__ out) {
    __shared__ float ssh[NN * CC];   // logits -> s, in place
    __shared__ float dsh[NN];
    __shared__ float wsh[CC], csh[CC], pbs[CC];
    __shared__ float sAcc[4];
    int b = blockIdx.x, t = threadIdx.x;
    int lane = t & 31;

    for (int i = t; i < NN * CC; i += 256) ssh[i] = g_logits[b * NN * CC + i];
    for (int i = t; i < NN; i += 256) dsh[i] = (float)g_deg[b * NN + i];
    if (t < CC) { wsh[t] = 0.f; csh[t] = 0.f; pbs[t] = pb[t]; }
    if (t < 4) sAcc[t] = 0.f;
    __syncthreads();

    // softmax per node (2 rows per thread), in place
    for (int r = t; r < NN; r += 256) {
        float* row = ssh + r * CC;
        float l[CC];
        float mx = -INFINITY;
        #pragma unroll
        for (int c = 0; c < CC; c++) { l[c] = row[c] + pbs[c]; mx = fmaxf(mx, l[c]); }
        float sum = 0.f;
        #pragma unroll
        for (int c = 0; c < CC; c++) { l[c] = expf(l[c] - mx); sum += l[c]; }
        float inv = 1.f / sum;
        #pragma unroll
        for (int c = 0; c < CC; c++) row[c] = l[c] * inv;
    }
    __syncthreads();

    float wp[CC] = {}, cp[CC] = {};
    float td = 0.f;
    for (int n = t; n < NN; n += 256) {
        float d = dsh[n];
        td += d;
        #pragma unroll
        for (int c = 0; c < CC; c++) {
            float sv = ssh[n * CC + c];
            wp[c] += sv * d;
            cp[c] += sv;
        }
    }
    td = warpSum(td);
    #pragma unroll
    for (int c = 0; c < CC; c++) { wp[c] = warpSum(wp[c]); cp[c] = warpSum(cp[c]); }
    if (lane == 0) {
        atomicAdd(&sAcc[0], td);
        #pragma unroll
        for (int c = 0; c < CC; c++) { atomicAdd(&wsh[c], wp[c]); atomicAdd(&csh[c], cp[c]); }
    }

    int cc = t >> 4, kk = t & 15;
    float ssv = 0.f;
    for (int n = 0; n < NN; n++) ssv += ssh[n * CC + cc] * ssh[n * CC + kk];
    float s2 = warpSum(ssv * ssv);
    if (lane == 0) atomicAdd(&sAcc[2], s2);

    const int* srcp = ei;
    const int* dstp = ei + ETOT;
    float et = 0.f;
    for (int e = b * EB + t; e < (b + 1) * EB; e += 256) {
        int sl = srcp[e] - b * NN;
        int dl = dstp[e] - b * NN;
        float d2 = 0.f;
        #pragma unroll
        for (int c = 0; c < CC; c++) d2 += ssh[sl * CC + c] * ssh[dl * CC + c];
        et += d2;
    }
    et = warpSum(et);
    if (lane == 0) atomicAdd(&sAcc[1], et);
    __syncthreads();

    float fro = sqrtf(sAcc[2]);
    float dd = ssv / fro - ((cc == kk) ? 0.25f : 0.f);
    float dsq = warpSum(dd * dd);
    if (lane == 0) atomicAdd(&sAcc[3], dsq);
    __syncthreads();

    if (t == 0) {
        float m = sAcc[0] * 0.5f;
        float wsq = 0.f, cs2 = 0.f;
        #pragma unroll
        for (int c = 0; c < CC; c++) { wsq += wsh[c] * wsh[c]; cs2 += csh[c] * csh[c]; }
        float trace = sAcc[1] - wsq / (2.f * m);
        float spec = -trace / (2.f * m);
        float ortho = sqrtf(sAcc[3]);
        float cluster = sqrtf(cs2) / (float)NN * 4.f - 1.f;
        atomicAdd(out, (spec + ortho + cluster) * (1.f / (float)BB));
    }
}

// ---------------- launch ----------------
extern "C" void kernel_launch(void* const* d_in, const int* in_sizes, int n_in,
                              void* d_out, int out_size) {
    const int*   x      = (const int*)d_in[0];
    const int*   ei     = (const int*)d_in[1];
    const float* emb    = (const float*)d_in[3];
    const float* w1     = (const float*)d_in[4];
    const float* b1     = (const float*)d_in[5];
    const float* bn_g   = (const float*)d_in[6];
    const float* bn_b   = (const float*)d_in[7];
    const float* bn_m   = (const float*)d_in[8];
    const float* bn_v   = (const float*)d_in[9];
    const float* w2     = (const float*)d_in[10];
    const float* b2     = (const float*)d_in[11];
    const float* pool_w = (const float*)d_in[12];
    const float* pool_b = (const float*)d_in[13];
    float* out = (float*)d_out;

    cudaFuncSetAttribute(gemm_mma<0>, cudaFuncAttributeMaxDynamicSharedMemorySize, SMEM_GEMM);
    cudaFuncSetAttribute(gemm_mma<1>, cudaFuncAttributeMaxDynamicSharedMemorySize, SMEM_GEMM);

    prep_kernel<<<(VOCAB * HD / 2 + 255) / 256, 256>>>(emb, w1, w2, out);
    edge_kernel<<<ETOT / 256, 256>>>(ei);
    z0_kernel<<<MROWS / 4, 256>>>(x);

    dim3 gGrid(HD / 128, MROWS / 128);   // (4, 256)
    gemm_mma<0><<<gGrid, 256, SMEM_GEMM>>>(b1, bn_g, bn_b, bn_m, bn_v, nullptr);
    gemm_mma<1><<<gGrid, 256, SMEM_GEMM>>>(b2, nullptr, nullptr, nullptr, nullptr, pool_w);

    loss_kernel<<<BB, 256>>>(ei, pool_b, out);
}

// round 13
// speedup vs baseline: 1.0466x; 1.0466x over previous
#include <cuda_runtime.h>
#include <cuda_fp16.h>
#include <math.h>
#include <stdint.h>

// Problem constants
#define BB    64
#define NN    512
#define MROWS (BB*NN)        // 32768 nodes
#define DEG   8
#define ETOT  (MROWS*DEG)    // 262144 edges
#define EB    (NN*DEG)       // 4096 edges per batch
#define HD    512            // D == H == 512
#define CC    16
#define VOCAB 10000
#define MAXD  64             // max in-degree capacity (Poisson(8); P(>=64) ~ 1e-40)
#define BN_EPS 1e-5f

#define ESCALE 64.0f         // emb e4m3 scale
#define IESC   (1.0f/64.0f)

// ---------------- static scratch ----------------
__device__ __align__(1024) uint8_t g_E8[VOCAB*HD];          // emb e4m3 (x64)
__device__ __align__(1024) __half g_A16[MROWS*HD];          // z0 fp16
__device__ __align__(1024) __half g_B16[MROWS*HD];          // z1 fp16
__device__ __align__(1024) __half g_W1[HD*HD];              // [n][k] fp16
__device__ __align__(1024) __half g_W2[HD*HD];
__device__ __align__(1024) float  g_logits[MROWS*CC];       // pre-softmax pool logits (self-cleaning)
__device__ int   g_deg[MROWS];                              // out-degree (self-cleaning)
__device__ int   g_cnt[MROWS];                              // in-degree cursor (self-cleaning)
__device__ int   g_slots[MROWS*MAXD];                       // src lists per dst (8 MB)

__device__ __forceinline__ float warpSum(float v) {
    #pragma unroll
    for (int o = 16; o; o >>= 1) v += __shfl_xor_sync(0xffffffffu, v, o);
    return v;
}

// ---------------- PTX helpers (sm_80+/sm_89+ portable) ----------------
__device__ __forceinline__ uint32_t smem_u32(const void* p) {
    uint32_t a;
    asm("{ .reg .u64 t; cvta.to.shared.u64 t, %1; cvt.u32.u64 %0, t; }" : "=r"(a) : "l"(p));
    return a;
}
__device__ __forceinline__ void cp16(uint32_t dst, const void* src) {
    asm volatile("cp.async.cg.shared.global [%0], [%1], 16;\n" :: "r"(dst), "l"(src));
}
__device__ __forceinline__ void cp_commit() {
    asm volatile("cp.async.commit_group;\n" ::: "memory");
}
template<int N>
__device__ __forceinline__ void cp_wait() {
    asm volatile("cp.async.wait_group %0;\n" :: "n"(N) : "memory");
}
__device__ __forceinline__ void ldm_x4(uint32_t* r, uint32_t addr) {
    asm volatile("ldmatrix.sync.aligned.m8n8.x4.shared.b16 {%0,%1,%2,%3}, [%4];"
                 : "=r"(r[0]), "=r"(r[1]), "=r"(r[2]), "=r"(r[3]) : "r"(addr));
}
__device__ __forceinline__ void mma16816(float* d, const uint32_t* a, const uint32_t* b) {
    asm volatile("mma.sync.aligned.m16n8k16.row.col.f32.f16.f16.f32 "
                 "{%0,%1,%2,%3}, {%4,%5,%6,%7}, {%8,%9}, {%0,%1,%2,%3};"
                 : "+f"(d[0]), "+f"(d[1]), "+f"(d[2]), "+f"(d[3])
                 : "r"(a[0]), "r"(a[1]), "r"(a[2]), "r"(a[3]), "r"(b[0]), "r"(b[1]));
}
__device__ __forceinline__ uint16_t fp8x2(float lo, float hi) {
    uint16_t r;
    asm("cvt.rn.satfinite.e4m3x2.f32 %0, %1, %2;" : "=h"(r) : "f"(hi), "f"(lo));
    return r;
}
__device__ __forceinline__ __half2 e4m3x2_h2(uint16_t v) {
    uint32_t r;
    asm("cvt.rn.f16x2.e4m3x2 %0, %1;" : "=r"(r) : "h"(v));
    return *(__half2*)&r;
}

// ---------------- single-pass edge processing: slots + degrees ----------------
// relies on g_cnt/g_deg zeroed (module load zero-init; re-zeroed by loss_kernel tail)
__global__ void edge_kernel(const int* __restrict__ ei) {
    int e = blockIdx.x * blockDim.x + threadIdx.x;
    if (e < ETOT) {
        int s = ei[e];
        int d = ei[ETOT + e];
        int p = atomicAdd(&g_cnt[d], 1);
        if (p < MAXD) g_slots[d * MAXD + p] = s;
        atomicAdd(&g_deg[s], 1);
    }
}

// ---------------- prep: emb->e4m3(x64) + W transpose fp16 + out=0 ----------------
__global__ void prep_kernel(const float* __restrict__ emb,
                            const float* __restrict__ w1, const float* __restrict__ w2,
                            float* out) {
    int i = blockIdx.x * blockDim.x + threadIdx.x;
    if (i < VOCAB * HD / 2) {
        float2 v = ((const float2*)emb)[i];
        ((uint16_t*)g_E8)[i] = fp8x2(v.x * ESCALE, v.y * ESCALE);
    }
    if (i < HD * HD) {       // i = k*512 + n
        int k = i >> 9, n = i & 511;
        g_W1[n * HD + k] = __float2half_rn(w1[i]);
        g_W2[n * HD + k] = __float2half_rn(w2[i]);
    }
    if (i == 0) out[0] = 0.f;
}

// ---------------- z0 = emb[x] + segment_sum(emb[x[src]], dst), fp16 out ----------------
// 4 nodes/block, 64 threads per node, 8 e4m3 bytes (uint2) per lane; hadd2 accumulate.
__global__ __launch_bounds__(256) void z0_kernel(const int* __restrict__ x) {
    __shared__ int s_sx[4][MAXD];
    __shared__ int s_meta[4][2];       // [cnt, self_token]
    int t = threadIdx.x;
    int sub = t >> 6, lane = t & 63;
    int n = blockIdx.x * 4 + sub;
    int cnt = min(g_cnt[n], MAXD);
    if (lane == 0) { s_meta[sub][0] = cnt; s_meta[sub][1] = x[n]; }
    if (lane < cnt) s_sx[sub][lane] = x[g_slots[n * MAXD + lane]];
    __syncthreads();

    const uint2* emb2 = (const uint2*)g_E8;    // 8 e4m3 per uint2, 64 per 512B row
    cnt = s_meta[sub][0];
    uint2 hv = emb2[(size_t)s_meta[sub][1] * 64 + lane];
    __half2 a0 = e4m3x2_h2((uint16_t)(hv.x & 0xffff));
    __half2 a1 = e4m3x2_h2((uint16_t)(hv.x >> 16));
    __half2 a2 = e4m3x2_h2((uint16_t)(hv.y & 0xffff));
    __half2 a3 = e4m3x2_h2((uint16_t)(hv.y >> 16));
    for (int e = 0; e < cnt; e++) {
        uint2 v = emb2[(size_t)s_sx[sub][e] * 64 + lane];
        a0 = __hadd2(a0, e4m3x2_h2((uint16_t)(v.x & 0xffff)));
        a1 = __hadd2(a1, e4m3x2_h2((uint16_t)(v.x >> 16)));
        a2 = __hadd2(a2, e4m3x2_h2((uint16_t)(v.y & 0xffff)));
        a3 = __hadd2(a3, e4m3x2_h2((uint16_t)(v.y >> 16)));
    }
    const __half2 sc = __floats2half2_rn(IESC, IESC);
    a0 = __hmul2(a0, sc); a1 = __hmul2(a1, sc);
    a2 = __hmul2(a2, sc); a3 = __hmul2(a3, sc);
    uint4 outv;
    *(__half2*)&outv.x = a0; *(__half2*)&outv.y = a1;
    *(__half2*)&outv.z = a2; *(__half2*)&outv.w = a3;
    ((uint4*)g_A16)[(size_t)n * 64 + lane] = outv;
}

// ---------------- mma.sync fp16 GEMM (R11 config: best measured) ----------------
// 128x128 CTA tile, 8 warps (2x4), warp tile 64x32, K-chunk 64, 3-stage cp.async, 2 CTAs/SM.
// WHICH==0: z1 = elu(bn(z0 @ w1 + b1)) -> g_B16 (fp16)
// WHICH==1: z2 = elu(z1 @ w2 + b2), fused pool: atomicAdd partial z2@pool_w logits

#define STAGE_BYTES 32768          // A 16K | W 16K
#define NSTAGE 3
#define SMEM_GEMM (NSTAGE * STAGE_BYTES)   // 96 KB

template<int WHICH>
__global__ __launch_bounds__(256, 2) void gemm_mma(
    const float* __restrict__ bias, const float* __restrict__ gamma,
    const float* __restrict__ beta, const float* __restrict__ mean,
    const float* __restrict__ var, const float* __restrict__ poolw)
{
    extern __shared__ __align__(1024) char smem[];
    const uint32_t sb = smem_u32(smem);
    const int tid = threadIdx.x;
    const int wid = tid >> 5, lane = tid & 31;
    const int wm = wid & 1;        // 0..1 -> 64 rows
    const int wn = wid >> 1;       // 0..3 -> 32 cols
    const int rowBase = blockIdx.y * 128;
    const int colBase = blockIdx.x * 128;

    const __half* __restrict__ Ap = WHICH ? g_B16 : g_A16;
    const __half* __restrict__ Wp = WHICH ? g_W2 : g_W1;

    // ---- loader: 8 x 16B cp.async per thread per chunk ----
    auto loadChunk = [&](int c, int s) {
        const uint32_t stage = sb + s * STAGE_BYTES;
        #pragma unroll
        for (int it = 0; it < 8; it++) {
            int idx = tid + it * 256;
            int q = idx >> 10;                    // 0=A, 1=W
            int r = (idx & 1023) >> 3;
            int cc = idx & 7;
            const __half* base = q ? Wp : Ap;
            int grow = (q ? colBase : rowBase) + r;
            const __half* src = base + (size_t)grow * HD + c * 64 + cc * 8;
            uint32_t off = r * 128 + cc * 16;
            uint32_t sw = off ^ ((off >> 3) & 0x70);
            cp16(stage + q * 16384 + sw, src);
        }
        cp_commit();
    };

    // ---- ldmatrix per-thread addressing ----
    const int g = lane >> 3;                  // 0..3
    const int aRowL = (g & 1) * 8 + (lane & 7);
    const int aKb   = (g >> 1);
    const int bRowL = (g >> 1) * 8 + (lane & 7);
    const int bKb   = (g & 1);

    uint32_t aRowOff[4], aXor[4];
    #pragma unroll
    for (int i = 0; i < 4; i++) {
        int ar = wm * 64 + i * 16 + aRowL;
        aRowOff[i] = ar * 128;
        aXor[i] = (ar & 7) << 4;
    }
    uint32_t bRowOff[2], bXor[2];
    #pragma unroll
    for (int p = 0; p < 2; p++) {
        int br = wn * 32 + p * 16 + bRowL;
        bRowOff[p] = br * 128;
        bXor[p] = (br & 7) << 4;
    }

    float acc[4][4][4] = {};

    loadChunk(0, 0);
    loadChunk(1, 1);

    for (int c = 0; c < 8; c++) {
        if (c < 7) cp_wait<1>(); else cp_wait<0>();
        __syncthreads();
        if (c + 2 < 8) loadChunk(c + 2, (c + 2) % NSTAGE);

        const uint32_t stage = sb + (c % NSTAGE) * STAGE_BYTES;
        const uint32_t aPl = stage, bPl = stage + 16384;

        #pragma unroll
        for (int s = 0; s < 4; s++) {          // k16 steps within 64-chunk
            uint32_t ah[4][4], bh[2][4];
            uint32_t aCol = (uint32_t)(s * 32 + aKb * 16);
            uint32_t bCol = (uint32_t)(s * 32 + bKb * 16);
            #pragma unroll
            for (int i = 0; i < 4; i++)
                ldm_x4(ah[i], aPl + aRowOff[i] + (aCol ^ aXor[i]));
            #pragma unroll
            for (int p = 0; p < 2; p++)
                ldm_x4(bh[p], bPl + bRowOff[p] + (bCol ^ bXor[p]));
            #pragma unroll
            for (int i = 0; i < 4; i++)
                #pragma unroll
                for (int j = 0; j < 4; j++)
                    mma16816(acc[i][j], ah[i], &bh[j >> 1][(j & 1) * 2]);
        }
    }
    __syncthreads();   // protect epilogue smem reuse against last chunk reads

    // ---- epilogue ----
    const int rlane = lane >> 2;
    const int clane = (lane & 3) * 2;
    float* sE = (float*)smem;                 // [128][129] for WHICH==1

    #pragma unroll
    for (int i = 0; i < 4; i++) {
        int rl0 = wm * 64 + i * 16 + rlane;
        #pragma unroll
        for (int j = 0; j < 4; j++) {
            int cl = wn * 32 + j * 8 + clane;
            int col = colBase + cl;
            float b0 = bias[col], b1v = bias[col + 1];
            float s0 = 1.f, s1 = 1.f, o0 = 0.f, o1 = 0.f;
            if (WHICH == 0) {
                s0 = rsqrtf(var[col] + BN_EPS) * gamma[col];
                s1 = rsqrtf(var[col + 1] + BN_EPS) * gamma[col + 1];
                o0 = beta[col] - mean[col] * s0;
                o1 = beta[col + 1] - mean[col + 1] * s1;
            }
            #pragma unroll
            for (int h = 0; h < 2; h++) {
                int rl = rl0 + h * 8;
                float v0 = acc[i][j][h * 2 + 0] + b0;
                float v1 = acc[i][j][h * 2 + 1] + b1v;
                if (WHICH == 0) { v0 = v0 * s0 + o0; v1 = v1 * s1 + o1; }
                v0 = v0 > 0.f ? v0 : expm1f(v0);
                v1 = v1 > 0.f ? v1 : expm1f(v1);
                if (WHICH == 0) {
                    *(__half2*)(g_B16 + (size_t)(rowBase + rl) * HD + col) =
                        __floats2half2_rn(v0, v1);
                } else {
                    sE[rl * 129 + cl] = v0;
                    sE[rl * 129 + cl + 1] = v1;
                }
            }
        }
    }

    if (WHICH == 1) {
        // fused pool: partial logits = sE(128x128) @ pool_w[colBase:colBase+128, 0:16]
        float* sPw = sE + 128 * 129;          // [128][16] = 8 KB
        __syncthreads();
        #pragma unroll
        for (int jj = 0; jj < 8; jj++) {
            int idx = tid * 8 + jj;
            int k = idx >> 4, cch = idx & 15;
            sPw[k * 16 + cch] = poolw[(size_t)(colBase + k) * CC + cch];
        }
        __syncthreads();
        int r = tid & 127;
        int c0 = (tid >> 7) * 8;
        float a8[8] = {};
        #pragma unroll 4
        for (int k = 0; k < 128; k++) {
            float zv = sE[r * 129 + k];
            #pragma unroll
            for (int c8 = 0; c8 < 8; c8++) a8[c8] += zv * sPw[k * 16 + c0 + c8];
        }
        float* dst = g_logits + (size_t)(rowBase + r) * CC + c0;
        #pragma unroll
        for (int c8 = 0; c8 < 8; c8++) atomicAdd(dst + c8, a8[c8]);
    }
}

// ---------------- per-batch losses (softmax fused; self-cleaning tail) ----------------
__global__ __launch_bounds__(256) void loss_kernel(const int* __restrict__ ei,
                                                   const float* __restrict__ pb,
                                                   float* __restrict__ out) {
    __shared__ float ssh[NN * CC];   // logits -> s, in place
    __shared__ float dsh[NN];
    __shared__ float wsh[CC], csh[CC], pbs[CC];
    __shared__ float sAcc[4];
    int b = blockIdx.x, t = threadIdx.x;
    int lane = t & 31;

    for (int i = t; i < NN * CC; i += 256) ssh[i] = g_logits[b * NN * CC + i];
    for (int i = t; i < NN; i += 256) dsh[i] = (float)g_deg[b * NN + i];
    if (t < CC) { wsh[t] = 0.f; csh[t] = 0.f; pbs[t] = pb[t]; }
    if (t < 4) sAcc[t] = 0.f;
    __syncthreads();

    // self-cleaning: zero this batch's counters + logits for the NEXT kernel_launch call
    // (reads above are complete; graph replays depend on this)
    for (int i = t; i < NN; i += 256) {
        int nb = b * NN + i;
        g_cnt[nb] = 0; g_deg[nb] = 0;
        float4 z = make_float4(0.f, 0.f, 0.f, 0.f);
        float4* lg = (float4*)(g_logits + (size_t)nb * CC);
        lg[0] = z; lg[1] = z; lg[2] = z; lg[3] = z;
    }

    // softmax per node (2 rows per thread), in place
    for (int r = t; r < NN; r += 256) {
        float* row = ssh + r * CC;
        float l[CC];
        float mx = -INFINITY;
        #pragma unroll
        for (int c = 0; c < CC; c++) { l[c] = row[c] + pbs[c]; mx = fmaxf(mx, l[c]); }
        float sum = 0.f;
        #pragma unroll
        for (int c = 0; c < CC; c++) { l[c] = expf(l[c] - mx); sum += l[c]; }
        float inv = 1.f / sum;
        #pragma unroll
        for (int c = 0; c < CC; c++) row[c] = l[c] * inv;
    }
    __syncthreads();

    float wp[CC] = {}, cp[CC] = {};
    float td = 0.f;
    for (int n = t; n < NN; n += 256) {
        float d = dsh[n];
        td += d;
        #pragma unroll
        for (int c = 0; c < CC; c++) {
            float sv = ssh[n * CC + c];
            wp[c] += sv * d;
            cp[c] += sv;
        }
    }
    td = warpSum(td);
    #pragma unroll
    for (int c = 0; c < CC; c++) { wp[c] = warpSum(wp[c]); cp[c] = warpSum(cp[c]); }
    if (lane == 0) {
        atomicAdd(&sAcc[0], td);
        #pragma unroll
        for (int c = 0; c < CC; c++) { atomicAdd(&wsh[c], wp[c]); atomicAdd(&csh[c], cp[c]); }
    }

    int cc = t >> 4, kk = t & 15;
    float ssv = 0.f;
    for (int n = 0; n < NN; n++) ssv += ssh[n * CC + cc] * ssh[n * CC + kk];
    float s2 = warpSum(ssv * ssv);
    if (lane == 0) atomicAdd(&sAcc[2], s2);

    const int* srcp = ei;
    const int* dstp = ei + ETOT;
    float et = 0.f;
    for (int e = b * EB + t; e < (b + 1) * EB; e += 256) {
        int sl = srcp[e] - b * NN;
        int dl = dstp[e] - b * NN;
        float d2 = 0.f;
        #pragma unroll
        for (int c = 0; c < CC; c++) d2 += ssh[sl * CC + c] * ssh[dl * CC + c];
        et += d2;
    }
    et = warpSum(et);
    if (lane == 0) atomicAdd(&sAcc[1], et);
    __syncthreads();

    float fro = sqrtf(sAcc[2]);
    float dd = ssv / fro - ((cc == kk) ? 0.25f : 0.f);
    float dsq = warpSum(dd * dd);
    if (lane == 0) atomicAdd(&sAcc[3], dsq);
    __syncthreads();

    if (t == 0) {
        float m = sAcc[0] * 0.5f;
        float wsq = 0.f, cs2 = 0.f;
        #pragma unroll
        for (int c = 0; c < CC; c++) { wsq += wsh[c] * wsh[c]; cs2 += csh[c] * csh[c]; }
        float trace = sAcc[1] - wsq / (2.f * m);
        float spec = -trace / (2.f * m);
        float ortho = sqrtf(sAcc[3]);
        float cluster = sqrtf(cs2) / (float)NN * 4.f - 1.f;
        atomicAdd(out, (spec + ortho + cluster) * (1.f / (float)BB));
    }
}

// ---------------- launch ----------------
extern "C" void kernel_launch(void* const* d_in, const int* in_sizes, int n_in,
                              void* d_out, int out_size) {
    const int*   x      = (const int*)d_in[0];
    const int*   ei     = (const int*)d_in[1];
    const float* emb    = (const float*)d_in[3];
    const float* w1     = (const float*)d_in[4];
    const float* b1     = (const float*)d_in[5];
    const float* bn_g   = (const float*)d_in[6];
    const float* bn_b   = (const float*)d_in[7];
    const float* bn_m   = (const float*)d_in[8];
    const float* bn_v   = (const float*)d_in[9];
    const float* w2     = (const float*)d_in[10];
    const float* b2     = (const float*)d_in[11];
    const float* pool_w = (const float*)d_in[12];
    const float* pool_b = (const float*)d_in[13];
    float* out = (float*)d_out;

    cudaFuncSetAttribute(gemm_mma<0>, cudaFuncAttributeMaxDynamicSharedMemorySize, SMEM_GEMM);
    cudaFuncSetAttribute(gemm_mma<1>, cudaFuncAttributeMaxDynamicSharedMemorySize, SMEM_GEMM);

    edge_kernel<<<ETOT / 256, 256>>>(ei);
    prep_kernel<<<(VOCAB * HD / 2 + 255) / 256, 256>>>(emb, w1, w2, out);
    z0_kernel<<<MROWS / 4, 256>>>(x);

    dim3 gGrid(HD / 128, MROWS / 128);   // (4, 256)
    gemm_mma<0><<<gGrid, 256, SMEM_GEMM>>>(b1, bn_g, bn_b, bn_m, bn_v, nullptr);
    gemm_mma<1><<<gGrid, 256, SMEM_GEMM>>>(b2, nullptr, nullptr, nullptr, nullptr, pool_w);

    loss_kernel<<<BB, 256>>>(ei, pool_b, out);
}

// round 14
// speedup vs baseline: 1.0467x; 1.0001x over previous
#include <cuda_runtime.h>
#include <cuda_fp16.h>
#include <math.h>
#include <stdint.h>

// Problem constants
#define BB    64
#define NN    512
#define MROWS (BB*NN)        // 32768 nodes
#define DEG   8
#define ETOT  (MROWS*DEG)    // 262144 edges
#define EB    (NN*DEG)       // 4096 edges per batch
#define HD    512            // D == H == 512
#define CC    16
#define VOCAB 10000
#define MAXD  64             // max in-degree capacity (Poisson(8); P(>=64) ~ 1e-40)
#define BN_EPS 1e-5f

#define ESCALE 64.0f         // emb e4m3 scale
#define IESC   (1.0f/64.0f)

// ---------------- static scratch ----------------
__device__ __align__(1024) uint8_t g_E8[VOCAB*HD];          // emb e4m3 (x64)
__device__ __align__(1024) __half g_A16[MROWS*HD];          // z0 fp16
__device__ __align__(1024) __half g_B16[MROWS*HD];          // z1 fp16
__device__ __align__(1024) __half g_W1[HD*HD];              // [n][k] fp16
__device__ __align__(1024) __half g_W2[HD*HD];
__device__ __align__(1024) float  g_logits[MROWS*CC];       // pool logits (self-cleaning)
__device__ float g_sc1[HD], g_of1[HD];                      // fused BN scale/offset for gemm0
__device__ int   g_deg[MROWS];                              // out-degree (self-cleaning)
__device__ int   g_cnt[MROWS];                              // in-degree cursor (self-cleaning)
__device__ int   g_slots[MROWS*MAXD];                       // src lists per dst (8 MB)

__device__ __forceinline__ float warpSum(float v) {
    #pragma unroll
    for (int o = 16; o; o >>= 1) v += __shfl_xor_sync(0xffffffffu, v, o);
    return v;
}

// ---------------- PTX helpers ----------------
__device__ __forceinline__ uint32_t smem_u32(const void* p) {
    uint32_t a;
    asm("{ .reg .u64 t; cvta.to.shared.u64 t, %1; cvt.u32.u64 %0, t; }" : "=r"(a) : "l"(p));
    return a;
}
__device__ __forceinline__ void cp16(uint32_t dst, const void* src) {
    asm volatile("cp.async.cg.shared.global [%0], [%1], 16;\n" :: "r"(dst), "l"(src));
}
__device__ __forceinline__ void cp_commit() {
    asm volatile("cp.async.commit_group;\n" ::: "memory");
}
template<int N>
__device__ __forceinline__ void cp_wait() {
    asm volatile("cp.async.wait_group %0;\n" :: "n"(N) : "memory");
}
__device__ __forceinline__ void ldm_x4(uint32_t* r, uint32_t addr) {
    asm volatile("ldmatrix.sync.aligned.m8n8.x4.shared.b16 {%0,%1,%2,%3}, [%4];"
                 : "=r"(r[0]), "=r"(r[1]), "=r"(r[2]), "=r"(r[3]) : "r"(addr));
}
__device__ __forceinline__ void mma16816(float* d, const uint32_t* a, const uint32_t* b) {
    asm volatile("mma.sync.aligned.m16n8k16.row.col.f32.f16.f16.f32 "
                 "{%0,%1,%2,%3}, {%4,%5,%6,%7}, {%8,%9}, {%0,%1,%2,%3};"
                 : "+f"(d[0]), "+f"(d[1]), "+f"(d[2]), "+f"(d[3])
                 : "r"(a[0]), "r"(a[1]), "r"(a[2]), "r"(a[3]), "r"(b[0]), "r"(b[1]));
}
__device__ __forceinline__ uint16_t fp8x2(float lo, float hi) {
    uint16_t r;
    asm("cvt.rn.satfinite.e4m3x2.f32 %0, %1, %2;" : "=h"(r) : "f"(hi), "f"(lo));
    return r;
}
__device__ __forceinline__ __half2 e4m3x2_h2(uint16_t v) {
    uint32_t r;
    asm("cvt.rn.f16x2.e4m3x2 %0, %1;" : "=r"(r) : "h"(v));
    return *(__half2*)&r;
}

// ---------------- prep: edges + emb->e4m3 + W transpose + BN fold + out=0 ----------------
// relies on g_cnt/g_deg zeroed (module-load zero-init; re-zeroed by loss_kernel tail)
__global__ void prep_kernel(const int* __restrict__ ei,
                            const float* __restrict__ emb,
                            const float* __restrict__ w1, const float* __restrict__ w2,
                            const float* __restrict__ b1,
                            const float* __restrict__ bn_g, const float* __restrict__ bn_b,
                            const float* __restrict__ bn_m, const float* __restrict__ bn_v,
                            float* out) {
    int i = blockIdx.x * blockDim.x + threadIdx.x;
    if (i < ETOT) {
        int s = ei[i];
        int d = ei[ETOT + i];
        int p = atomicAdd(&g_cnt[d], 1);
        if (p < MAXD) g_slots[d * MAXD + p] = s;
        atomicAdd(&g_deg[s], 1);
    }
    if (i < VOCAB * HD / 2) {
        float2 v = ((const float2*)emb)[i];
        ((uint16_t*)g_E8)[i] = fp8x2(v.x * ESCALE, v.y * ESCALE);
    }
    if (i < HD * HD) {       // i = k*512 + n
        int k = i >> 9, n = i & 511;
        g_W1[n * HD + k] = __float2half_rn(w1[i]);
        g_W2[n * HD + k] = __float2half_rn(w2[i]);
    }
    if (i < HD) {
        float s0 = rsqrtf(bn_v[i] + BN_EPS) * bn_g[i];
        g_sc1[i] = s0;
        g_of1[i] = (b1[i] - bn_m[i]) * s0 + bn_b[i];
    }
    if (i == 0) out[0] = 0.f;
}

// ---------------- z0 = emb[x] + segment_sum(emb[x[src]], dst), fp16 out ----------------
__global__ __launch_bounds__(256) void z0_kernel(const int* __restrict__ x) {
    __shared__ int s_sx[4][MAXD];
    __shared__ int s_meta[4][2];       // [cnt, self_token]
    int t = threadIdx.x;
    int sub = t >> 6, lane = t & 63;
    int n = blockIdx.x * 4 + sub;
    int cnt = min(g_cnt[n], MAXD);
    if (lane == 0) { s_meta[sub][0] = cnt; s_meta[sub][1] = x[n]; }
    if (lane < cnt) s_sx[sub][lane] = x[g_slots[n * MAXD + lane]];
    __syncthreads();

    const uint2* emb2 = (const uint2*)g_E8;    // 8 e4m3 per uint2, 64 per 512B row
    cnt = s_meta[sub][0];
    uint2 hv = emb2[(size_t)s_meta[sub][1] * 64 + lane];
    __half2 a0 = e4m3x2_h2((uint16_t)(hv.x & 0xffff));
    __half2 a1 = e4m3x2_h2((uint16_t)(hv.x >> 16));
    __half2 a2 = e4m3x2_h2((uint16_t)(hv.y & 0xffff));
    __half2 a3 = e4m3x2_h2((uint16_t)(hv.y >> 16));
    for (int e = 0; e < cnt; e++) {
        uint2 v = emb2[(size_t)s_sx[sub][e] * 64 + lane];
        a0 = __hadd2(a0, e4m3x2_h2((uint16_t)(v.x & 0xffff)));
        a1 = __hadd2(a1, e4m3x2_h2((uint16_t)(v.x >> 16)));
        a2 = __hadd2(a2, e4m3x2_h2((uint16_t)(v.y & 0xffff)));
        a3 = __hadd2(a3, e4m3x2_h2((uint16_t)(v.y >> 16)));
    }
    const __half2 sc = __floats2half2_rn(IESC, IESC);
    a0 = __hmul2(a0, sc); a1 = __hmul2(a1, sc);
    a2 = __hmul2(a2, sc); a3 = __hmul2(a3, sc);
    uint4 outv;
    *(__half2*)&outv.x = a0; *(__half2*)&outv.y = a1;
    *(__half2*)&outv.z = a2; *(__half2*)&outv.w = a3;
    ((uint4*)g_A16)[(size_t)n * 64 + lane] = outv;
}

// ---------------- mma.sync fp16 GEMM, high-occupancy config ----------------
// CTA tile 128x64, 8 warps (4x2), warp tile 32x32, K-chunk 64, 3-stage, 3 CTAs/SM.
// WHICH==0: z1 = elu(bn(z0 @ w1 + b1)) -> g_B16 (fp16)   [BN prefolded: v*sc + of]
// WHICH==1: z2 = elu(z1 @ w2 + b2), fused pool partial logits

#define STAGE_BYTES 24576          // A 16K | W 8K
#define NSTAGE 3
#define SMEM_GEMM (NSTAGE * STAGE_BYTES)   // 72 KB -> 3 CTAs/SM

template<int WHICH>
__global__ __launch_bounds__(256, 3) void gemm_mma(
    const float* __restrict__ bias2, const float* __restrict__ poolw)
{
    extern __shared__ __align__(1024) char smem[];
    const uint32_t sb = smem_u32(smem);
    const int tid = threadIdx.x;
    const int wid = tid >> 5, lane = tid & 31;
    const int wm = wid & 3;        // 0..3 -> 32-row groups
    const int wn = wid >> 2;       // 0..1 -> 32-col groups
    const int rowBase = blockIdx.y * 128;
    const int colBase = blockIdx.x * 64;

    const __half* __restrict__ Ap = WHICH ? g_B16 : g_A16;
    const __half* __restrict__ Wp = WHICH ? g_W2 : g_W1;

    // ---- loader: 6 x 16B cp.async per thread per chunk (A 1024 + W 512 items) ----
    auto loadChunk = [&](int c, int s) {
        const uint32_t stage = sb + s * STAGE_BYTES;
        #pragma unroll
        for (int it = 0; it < 6; it++) {
            int idx = tid + it * 256;
            const __half* src;
            uint32_t dstOfs;
            int r, cc;
            if (idx < 1024) {                  // A: 128 rows x 8 chunks
                r = idx >> 3; cc = idx & 7;
                src = Ap + (size_t)(rowBase + r) * HD + c * 64 + cc * 8;
                dstOfs = 0;
            } else {                           // W: 64 rows x 8 chunks
                int w = idx - 1024;
                r = w >> 3; cc = w & 7;
                src = Wp + (size_t)(colBase + r) * HD + c * 64 + cc * 8;
                dstOfs = 16384;
            }
            uint32_t off = r * 128 + cc * 16;
            uint32_t sw = off ^ ((off >> 3) & 0x70);
            cp16(stage + dstOfs + sw, src);
        }
        cp_commit();
    };

    // ---- ldmatrix per-thread addressing ----
    const int g = lane >> 3;                  // 0..3
    const int aRowL = (g & 1) * 8 + (lane & 7);
    const int aKb   = (g >> 1);
    const int bRowL = (g >> 1) * 8 + (lane & 7);
    const int bKb   = (g & 1);

    uint32_t aRowOff[2], aXor[2];
    #pragma unroll
    for (int i = 0; i < 2; i++) {
        int ar = wm * 32 + i * 16 + aRowL;
        aRowOff[i] = ar * 128;
        aXor[i] = (ar & 7) << 4;
    }
    uint32_t bRowOff[2], bXor[2];
    #pragma unroll
    for (int p = 0; p < 2; p++) {
        int br = wn * 32 + p * 16 + bRowL;
        bRowOff[p] = br * 128;
        bXor[p] = (br & 7) << 4;
    }

    float acc[2][4][4] = {};

    loadChunk(0, 0);
    loadChunk(1, 1);

    for (int c = 0; c < 8; c++) {
        if (c < 7) cp_wait<1>(); else cp_wait<0>();
        __syncthreads();
        if (c + 2 < 8) loadChunk(c + 2, (c + 2) % NSTAGE);

        const uint32_t stage = sb + (c % NSTAGE) * STAGE_BYTES;
        const uint32_t aPl = stage, bPl = stage + 16384;

        #pragma unroll
        for (int s = 0; s < 4; s++) {          // k16 steps within 64-chunk
            uint32_t ah[2][4], bh[2][4];
            uint32_t aCol = (uint32_t)(s * 32 + aKb * 16);
            uint32_t bCol = (uint32_t)(s * 32 + bKb * 16);
            #pragma unroll
            for (int i = 0; i < 2; i++)
                ldm_x4(ah[i], aPl + aRowOff[i] + (aCol ^ aXor[i]));
            #pragma unroll
            for (int p = 0; p < 2; p++)
                ldm_x4(bh[p], bPl + bRowOff[p] + (bCol ^ bXor[p]));
            #pragma unroll
            for (int i = 0; i < 2; i++)
                #pragma unroll
                for (int j = 0; j < 4; j++)
                    mma16816(acc[i][j], ah[i], &bh[j >> 1][(j & 1) * 2]);
        }
    }
    __syncthreads();   // protect epilogue smem reuse against last chunk reads

    // ---- epilogue ----
    const int rlane = lane >> 2;
    const int clane = (lane & 3) * 2;
    float* sE = (float*)smem;                 // [128][65] for WHICH==1

    #pragma unroll
    for (int i = 0; i < 2; i++) {
        int rl0 = wm * 32 + i * 16 + rlane;
        #pragma unroll
        for (int j = 0; j < 4; j++) {
            int cl = wn * 32 + j * 8 + clane;
            int col = colBase + cl;
            float s0, s1, o0, o1;
            if (WHICH == 0) {
                s0 = g_sc1[col]; s1 = g_sc1[col + 1];
                o0 = g_of1[col]; o1 = g_of1[col + 1];
            } else {
                s0 = 1.f; s1 = 1.f;
                o0 = bias2[col]; o1 = bias2[col + 1];
            }
            #pragma unroll
            for (int h = 0; h < 2; h++) {
                int rl = rl0 + h * 8;
                float v0 = acc[i][j][h * 2 + 0] * s0 + o0;
                float v1 = acc[i][j][h * 2 + 1] * s1 + o1;
                v0 = v0 > 0.f ? v0 : expm1f(v0);
                v1 = v1 > 0.f ? v1 : expm1f(v1);
                if (WHICH == 0) {
                    *(__half2*)(g_B16 + (size_t)(rowBase + rl) * HD + col) =
                        __floats2half2_rn(v0, v1);
                } else {
                    sE[rl * 65 + cl] = v0;
                    sE[rl * 65 + cl + 1] = v1;
                }
            }
        }
    }

    if (WHICH == 1) {
        // fused pool: partial logits = sE(128x64) @ pool_w[colBase:colBase+64, 0:16]
        float* sPw = sE + 128 * 65;           // [64][16] = 4 KB
        __syncthreads();
        #pragma unroll
        for (int jj = 0; jj < 4; jj++) {
            int idx = tid * 4 + jj;
            int k = idx >> 4, cch = idx & 15;
            sPw[k * 16 + cch] = poolw[(size_t)(colBase + k) * CC + cch];
        }
        __syncthreads();
        int r = tid & 127;
        int c0 = (tid >> 7) * 8;
        float a8[8] = {};
        #pragma unroll 4
        for (int k = 0; k < 64; k++) {
            float zv = sE[r * 65 + k];
            #pragma unroll
            for (int c8 = 0; c8 < 8; c8++) a8[c8] += zv * sPw[k * 16 + c0 + c8];
        }
        float* dst = g_logits + (size_t)(rowBase + r) * CC + c0;
        #pragma unroll
        for (int c8 = 0; c8 < 8; c8++) atomicAdd(dst + c8, a8[c8]);
    }
}

// ---------------- per-batch losses (softmax fused; self-cleaning tail) ----------------
__global__ __launch_bounds__(256) void loss_kernel(const int* __restrict__ ei,
                                                   const float* __restrict__ pb,
                                                   float* __restrict__ out) {
    __shared__ float ssh[NN * CC];   // logits -> s, in place
    __shared__ float dsh[NN];
    __shared__ float wsh[CC], csh[CC], pbs[CC];
    __shared__ float sAcc[4];
    int b = blockIdx.x, t = threadIdx.x;
    int lane = t & 31;

    for (int i = t; i < NN * CC; i += 256) ssh[i] = g_logits[b * NN * CC + i];
    for (int i = t; i < NN; i += 256) dsh[i] = (float)g_deg[b * NN + i];
    if (t < CC) { wsh[t] = 0.f; csh[t] = 0.f; pbs[t] = pb[t]; }
    if (t < 4) sAcc[t] = 0.f;
    __syncthreads();

    // self-cleaning for the next kernel_launch call / graph replay
    for (int i = t; i < NN; i += 256) {
        int nb = b * NN + i;
        g_cnt[nb] = 0; g_deg[nb] = 0;
        float4 z = make_float4(0.f, 0.f, 0.f, 0.f);
        float4* lg = (float4*)(g_logits + (size_t)nb * CC);
        lg[0] = z; lg[1] = z; lg[2] = z; lg[3] = z;
    }

    // softmax per node (2 rows per thread), in place
    for (int r = t; r < NN; r += 256) {
        float* row = ssh + r * CC;
        float l[CC];
        float mx = -INFINITY;
        #pragma unroll
        for (int c = 0; c < CC; c++) { l[c] = row[c] + pbs[c]; mx = fmaxf(mx, l[c]); }
        float sum = 0.f;
        #pragma unroll
        for (int c = 0; c < CC; c++) { l[c] = expf(l[c] - mx); sum += l[c]; }
        float inv = 1.f / sum;
        #pragma unroll
        for (int c = 0; c < CC; c++) row[c] = l[c] * inv;
    }
    __syncthreads();

    float wp[CC] = {}, cp[CC] = {};
    float td = 0.f;
    for (int n = t; n < NN; n += 256) {
        float d = dsh[n];
        td += d;
        #pragma unroll
        for (int c = 0; c < CC; c++) {
            float sv = ssh[n * CC + c];
            wp[c] += sv * d;
            cp[c] += sv;
        }
    }
    td = warpSum(td);
    #pragma unroll
    for (int c = 0; c < CC; c++) { wp[c] = warpSum(wp[c]); cp[c] = warpSum(cp[c]); }
    if (lane == 0) {
        atomicAdd(&sAcc[0], td);
        #pragma unroll
        for (int c = 0; c < CC; c++) { atomicAdd(&wsh[c], wp[c]); atomicAdd(&csh[c], cp[c]); }
    }

    int cc = t >> 4, kk = t & 15;
    float ssv = 0.f;
    for (int n = 0; n < NN; n++) ssv += ssh[n * CC + cc] * ssh[n * CC + kk];
    float s2 = warpSum(ssv * ssv);
    if (lane == 0) atomicAdd(&sAcc[2], s2);

    const int* srcp = ei;
    const int* dstp = ei + ETOT;
    float et = 0.f;
    for (int e = b * EB + t; e < (b + 1) * EB; e += 256) {
        int sl = srcp[e] - b * NN;
        int dl = dstp[e] - b * NN;
        float d2 = 0.f;
        #pragma unroll
        for (int c = 0; c < CC; c++) d2 += ssh[sl * CC + c] * ssh[dl * CC + c];
        et += d2;
    }
    et = warpSum(et);
    if (lane == 0) atomicAdd(&sAcc[1], et);
    __syncthreads();

    float fro = sqrtf(sAcc[2]);
    float dd = ssv / fro - ((cc == kk) ? 0.25f : 0.f);
    float dsq = warpSum(dd * dd);
    if (lane == 0) atomicAdd(&sAcc[3], dsq);
    __syncthreads();

    if (t == 0) {
        float m = sAcc[0] * 0.5f;
        float wsq = 0.f, cs2 = 0.f;
        #pragma unroll
        for (int c = 0; c < CC; c++) { wsq += wsh[c] * wsh[c]; cs2 += csh[c] * csh[c]; }
        float trace = sAcc[1] - wsq / (2.f * m);
        float spec = -trace / (2.f * m);
        float ortho = sqrtf(sAcc[3]);
        float cluster = sqrtf(cs2) / (float)NN * 4.f - 1.f;
        atomicAdd(out, (spec + ortho + cluster) * (1.f / (float)BB));
    }
}

// ---------------- launch ----------------
extern "C" void kernel_launch(void* const* d_in, const int* in_sizes, int n_in,
                              void* d_out, int out_size) {
    const int*   x      = (const int*)d_in[0];
    const int*   ei     = (const int*)d_in[1];
    const float* emb    = (const float*)d_in[3];
    const float* w1     = (const float*)d_in[4];
    const float* b1     = (const float*)d_in[5];
    const float* bn_g   = (const float*)d_in[6];
    const float* bn_b   = (const float*)d_in[7];
    const float* bn_m   = (const float*)d_in[8];
    const float* bn_v   = (const float*)d_in[9];
    const float* w2     = (const float*)d_in[10];
    const float* b2     = (const float*)d_in[11];
    const float* pool_w = (const float*)d_in[12];
    const float* pool_b = (const float*)d_in[13];
    float* out = (float*)d_out;

    cudaFuncSetAttribute(gemm_mma<0>, cudaFuncAttributeMaxDynamicSharedMemorySize, SMEM_GEMM);
    cudaFuncSetAttribute(gemm_mma<1>, cudaFuncAttributeMaxDynamicSharedMemorySize, SMEM_GEMM);

    prep_kernel<<<(VOCAB * HD / 2 + 255) / 256, 256>>>(ei, emb, w1, w2, b1,
                                                       bn_g, bn_b, bn_m, bn_v, out);
    z0_kernel<<<MROWS / 4, 256>>>(x);

    dim3 gGrid(HD / 64, MROWS / 128);   // (8, 256)
    gemm_mma<0><<<gGrid, 256, SMEM_GEMM>>>(nullptr, nullptr);
    gemm_mma<1><<<gGrid, 256, SMEM_GEMM>>>(b2, pool_w);

    loss_kernel<<<BB, 256>>>(ei, pool_b, out);
}

// round 15
// speedup vs baseline: 1.0541x; 1.0070x over previous
#include <cuda_runtime.h>
#include <cuda_fp16.h>
#include <math.h>
#include <stdint.h>

// Problem constants
#define BB    64
#define NN    512
#define MROWS (BB*NN)        // 32768 nodes
#define DEG   8
#define ETOT  (MROWS*DEG)    // 262144 edges
#define EB    (NN*DEG)       // 4096 edges per batch
#define HD    512            // D == H == 512
#define CC    16
#define VOCAB 10000
#define MAXD  64             // max in-degree capacity (Poisson(8); P(>=64) ~ 1e-40)
#define BN_EPS 1e-5f

#define ESCALE 64.0f         // emb e4m3 scale
#define IESC   (1.0f/64.0f)

// ---------------- static scratch ----------------
__device__ __align__(1024) uint8_t g_E8[VOCAB*HD];          // emb e4m3 (x64)
__device__ __align__(1024) __half g_A16[MROWS*HD];          // z0 fp16
__device__ __align__(1024) __half g_B16[MROWS*HD];          // z1 fp16
__device__ __align__(1024) __half g_W1[HD*HD];              // [n][k] fp16
__device__ __align__(1024) __half g_W2[HD*HD];
__device__ __align__(1024) float  g_logits[MROWS*CC];       // pool logits (self-cleaning)
__device__ float g_sc1[HD], g_of1[HD];                      // fused BN scale/offset for gemm0
__device__ int   g_deg[MROWS];                              // out-degree (self-cleaning)
__device__ int   g_cnt[MROWS];                              // in-degree cursor (self-cleaning)
__device__ int   g_slots[MROWS*MAXD];                       // src lists per dst (8 MB)

__device__ __forceinline__ float warpSum(float v) {
    #pragma unroll
    for (int o = 16; o; o >>= 1) v += __shfl_xor_sync(0xffffffffu, v, o);
    return v;
}

// ---------------- PTX helpers ----------------
__device__ __forceinline__ uint32_t smem_u32(const void* p) {
    uint32_t a;
    asm("{ .reg .u64 t; cvta.to.shared.u64 t, %1; cvt.u32.u64 %0, t; }" : "=r"(a) : "l"(p));
    return a;
}
__device__ __forceinline__ void cp16(uint32_t dst, const void* src) {
    asm volatile("cp.async.cg.shared.global [%0], [%1], 16;\n" :: "r"(dst), "l"(src));
}
__device__ __forceinline__ void cp_commit() {
    asm volatile("cp.async.commit_group;\n" ::: "memory");
}
template<int N>
__device__ __forceinline__ void cp_wait() {
    asm volatile("cp.async.wait_group %0;\n" :: "n"(N) : "memory");
}
__device__ __forceinline__ void ldm_x4(uint32_t* r, uint32_t addr) {
    asm volatile("ldmatrix.sync.aligned.m8n8.x4.shared.b16 {%0,%1,%2,%3}, [%4];"
                 : "=r"(r[0]), "=r"(r[1]), "=r"(r[2]), "=r"(r[3]) : "r"(addr));
}
__device__ __forceinline__ void mma16816(float* d, const uint32_t* a, const uint32_t* b) {
    asm volatile("mma.sync.aligned.m16n8k16.row.col.f32.f16.f16.f32 "
                 "{%0,%1,%2,%3}, {%4,%5,%6,%7}, {%8,%9}, {%0,%1,%2,%3};"
                 : "+f"(d[0]), "+f"(d[1]), "+f"(d[2]), "+f"(d[3])
                 : "r"(a[0]), "r"(a[1]), "r"(a[2]), "r"(a[3]), "r"(b[0]), "r"(b[1]));
}
__device__ __forceinline__ uint16_t fp8x2(float lo, float hi) {
    uint16_t r;
    asm("cvt.rn.satfinite.e4m3x2.f32 %0, %1, %2;" : "=h"(r) : "f"(hi), "f"(lo));
    return r;
}
__device__ __forceinline__ __half2 e4m3x2_h2(uint16_t v) {
    uint32_t r;
    asm("cvt.rn.f16x2.e4m3x2 %0, %1;" : "=r"(r) : "h"(v));
    return *(__half2*)&r;
}

// ---------------- prep: edges + emb->e4m3 + W transpose + BN fold + out=0 ----------------
__global__ void prep_kernel(const int* __restrict__ ei,
                            const float* __restrict__ emb,
                            const float* __restrict__ w1, const float* __restrict__ w2,
                            const float* __restrict__ b1,
                            const float* __restrict__ bn_g, const float* __restrict__ bn_b,
                            const float* __restrict__ bn_m, const float* __restrict__ bn_v,
                            float* out) {
    int i = blockIdx.x * blockDim.x + threadIdx.x;
    if (i < ETOT) {
        int s = ei[i];
        int d = ei[ETOT + i];
        int p = atomicAdd(&g_cnt[d], 1);
        if (p < MAXD) g_slots[d * MAXD + p] = s;
        atomicAdd(&g_deg[s], 1);
    }
    if (i < VOCAB * HD / 2) {
        float2 v = ((const float2*)emb)[i];
        ((uint16_t*)g_E8)[i] = fp8x2(v.x * ESCALE, v.y * ESCALE);
    }
    if (i < HD * HD) {       // i = k*512 + n
        int k = i >> 9, n = i & 511;
        g_W1[n * HD + k] = __float2half_rn(w1[i]);
        g_W2[n * HD + k] = __float2half_rn(w2[i]);
    }
    if (i < HD) {
        float s0 = rsqrtf(bn_v[i] + BN_EPS) * bn_g[i];
        g_sc1[i] = s0;
        g_of1[i] = (b1[i] - bn_m[i]) * s0 + bn_b[i];
    }
    if (i == 0) out[0] = 0.f;
}

// ---------------- z0 = emb[x] + segment_sum(emb[x[src]], dst), fp16 out ----------------
__global__ __launch_bounds__(256) void z0_kernel(const int* __restrict__ x) {
    __shared__ int s_sx[4][MAXD];
    __shared__ int s_meta[4][2];
    int t = threadIdx.x;
    int sub = t >> 6, lane = t & 63;
    int n = blockIdx.x * 4 + sub;
    int cnt = min(g_cnt[n], MAXD);
    if (lane == 0) { s_meta[sub][0] = cnt; s_meta[sub][1] = x[n]; }
    if (lane < cnt) s_sx[sub][lane] = x[g_slots[n * MAXD + lane]];
    __syncthreads();

    const uint2* emb2 = (const uint2*)g_E8;
    cnt = s_meta[sub][0];
    uint2 hv = emb2[(size_t)s_meta[sub][1] * 64 + lane];
    __half2 a0 = e4m3x2_h2((uint16_t)(hv.x & 0xffff));
    __half2 a1 = e4m3x2_h2((uint16_t)(hv.x >> 16));
    __half2 a2 = e4m3x2_h2((uint16_t)(hv.y & 0xffff));
    __half2 a3 = e4m3x2_h2((uint16_t)(hv.y >> 16));
    for (int e = 0; e < cnt; e++) {
        uint2 v = emb2[(size_t)s_sx[sub][e] * 64 + lane];
        a0 = __hadd2(a0, e4m3x2_h2((uint16_t)(v.x & 0xffff)));
        a1 = __hadd2(a1, e4m3x2_h2((uint16_t)(v.x >> 16)));
        a2 = __hadd2(a2, e4m3x2_h2((uint16_t)(v.y & 0xffff)));
        a3 = __hadd2(a3, e4m3x2_h2((uint16_t)(v.y >> 16)));
    }
    const __half2 sc = __floats2half2_rn(IESC, IESC);
    a0 = __hmul2(a0, sc); a1 = __hmul2(a1, sc);
    a2 = __hmul2(a2, sc); a3 = __hmul2(a3, sc);
    uint4 outv;
    *(__half2*)&outv.x = a0; *(__half2*)&outv.y = a1;
    *(__half2*)&outv.z = a2; *(__half2*)&outv.w = a3;
    ((uint4*)g_A16)[(size_t)n * 64 + lane] = outv;
}

// ================= gemm0: z1 = elu(bn(z0 @ w1)) =================
// CTA 128x64, 8 warps (4x2), warp 32x32, 3-stage x 24KB, 3 CTAs/SM. (R14-measured win)
#define ST0 24576
#define SM0 (3 * ST0)        // 72 KB

__global__ __launch_bounds__(256, 3) void gemm0_kernel() {
    extern __shared__ __align__(1024) char smem[];
    const uint32_t sb = smem_u32(smem);
    const int tid = threadIdx.x;
    const int wid = tid >> 5, lane = tid & 31;
    const int wm = wid & 3;        // 0..3 -> 32-row groups
    const int wn = wid >> 2;       // 0..1 -> 32-col groups
    const int rowBase = blockIdx.y * 128;
    const int colBase = blockIdx.x * 64;

    auto loadChunk = [&](int c, int s) {
        const uint32_t stage = sb + s * ST0;
        #pragma unroll
        for (int it = 0; it < 6; it++) {
            int idx = tid + it * 256;
            const __half* src;
            uint32_t dstOfs;
            int r, cc;
            if (idx < 1024) {                  // A: 128 rows
                r = idx >> 3; cc = idx & 7;
                src = g_A16 + (size_t)(rowBase + r) * HD + c * 64 + cc * 8;
                dstOfs = 0;
            } else {                           // W: 64 rows
                int w = idx - 1024;
                r = w >> 3; cc = w & 7;
                src = g_W1 + (size_t)(colBase + r) * HD + c * 64 + cc * 8;
                dstOfs = 16384;
            }
            uint32_t off = r * 128 + cc * 16;
            uint32_t sw = off ^ ((off >> 3) & 0x70);
            cp16(stage + dstOfs + sw, src);
        }
        cp_commit();
    };

    const int g = lane >> 3;
    const int aRowL = (g & 1) * 8 + (lane & 7);
    const int aKb   = (g >> 1);
    const int bRowL = (g >> 1) * 8 + (lane & 7);
    const int bKb   = (g & 1);

    uint32_t aRowOff[2], aXor[2];
    #pragma unroll
    for (int i = 0; i < 2; i++) {
        int ar = wm * 32 + i * 16 + aRowL;
        aRowOff[i] = ar * 128; aXor[i] = (ar & 7) << 4;
    }
    uint32_t bRowOff[2], bXor[2];
    #pragma unroll
    for (int p = 0; p < 2; p++) {
        int br = wn * 32 + p * 16 + bRowL;
        bRowOff[p] = br * 128; bXor[p] = (br & 7) << 4;
    }

    float acc[2][4][4] = {};
    loadChunk(0, 0);
    loadChunk(1, 1);

    for (int c = 0; c < 8; c++) {
        if (c < 7) cp_wait<1>(); else cp_wait<0>();
        __syncthreads();
        if (c + 2 < 8) loadChunk(c + 2, (c + 2) % 3);

        const uint32_t stage = sb + (c % 3) * ST0;
        const uint32_t aPl = stage, bPl = stage + 16384;

        #pragma unroll
        for (int s = 0; s < 4; s++) {
            uint32_t ah[2][4], bh[2][4];
            uint32_t aCol = (uint32_t)(s * 32 + aKb * 16);
            uint32_t bCol = (uint32_t)(s * 32 + bKb * 16);
            #pragma unroll
            for (int i = 0; i < 2; i++)
                ldm_x4(ah[i], aPl + aRowOff[i] + (aCol ^ aXor[i]));
            #pragma unroll
            for (int p = 0; p < 2; p++)
                ldm_x4(bh[p], bPl + bRowOff[p] + (bCol ^ bXor[p]));
            #pragma unroll
            for (int i = 0; i < 2; i++)
                #pragma unroll
                for (int j = 0; j < 4; j++)
                    mma16816(acc[i][j], ah[i], &bh[j >> 1][(j & 1) * 2]);
        }
    }

    const int rlane = lane >> 2;
    const int clane = (lane & 3) * 2;
    #pragma unroll
    for (int i = 0; i < 2; i++) {
        int rl0 = wm * 32 + i * 16 + rlane;
        #pragma unroll
        for (int j = 0; j < 4; j++) {
            int cl = wn * 32 + j * 8 + clane;
            int col = colBase + cl;
            float s0 = g_sc1[col], s1 = g_sc1[col + 1];
            float o0 = g_of1[col], o1 = g_of1[col + 1];
            #pragma unroll
            for (int h = 0; h < 2; h++) {
                int rl = rl0 + h * 8;
                float v0 = acc[i][j][h * 2 + 0] * s0 + o0;
                float v1 = acc[i][j][h * 2 + 1] * s1 + o1;
                v0 = v0 > 0.f ? v0 : expm1f(v0);
                v1 = v1 > 0.f ? v1 : expm1f(v1);
                *(__half2*)(g_B16 + (size_t)(rowBase + rl) * HD + col) =
                    __floats2half2_rn(v0, v1);
            }
        }
    }
}

// ================= gemm1: z2 = elu(z1 @ w2 + b2) + fused pool =================
// CTA 128x128, 8 warps (2x4), warp 64x32, 3-stage x 32KB, 2 CTAs/SM. (R13-measured best)
#define ST1 32768
#define SM1 (3 * ST1)        // 96 KB

__global__ __launch_bounds__(256, 2) void gemm1_kernel(
    const float* __restrict__ bias2, const float* __restrict__ poolw)
{
    extern __shared__ __align__(1024) char smem[];
    const uint32_t sb = smem_u32(smem);
    const int tid = threadIdx.x;
    const int wid = tid >> 5, lane = tid & 31;
    const int wm = wid & 1;        // 0..1 -> 64 rows
    const int wn = wid >> 1;       // 0..3 -> 32 cols
    const int rowBase = blockIdx.y * 128;
    const int colBase = blockIdx.x * 128;

    auto loadChunk = [&](int c, int s) {
        const uint32_t stage = sb + s * ST1;
        #pragma unroll
        for (int it = 0; it < 8; it++) {
            int idx = tid + it * 256;
            int q = idx >> 10;                    // 0=A, 1=W
            int r = (idx & 1023) >> 3;
            int cc = idx & 7;
            const __half* base = q ? g_W2 : g_B16;
            int grow = (q ? colBase : rowBase) + r;
            const __half* src = base + (size_t)grow * HD + c * 64 + cc * 8;
            uint32_t off = r * 128 + cc * 16;
            uint32_t sw = off ^ ((off >> 3) & 0x70);
            cp16(stage + q * 16384 + sw, src);
        }
        cp_commit();
    };

    const int g = lane >> 3;
    const int aRowL = (g & 1) * 8 + (lane & 7);
    const int aKb   = (g >> 1);
    const int bRowL = (g >> 1) * 8 + (lane & 7);
    const int bKb   = (g & 1);

    uint32_t aRowOff[4], aXor[4];
    #pragma unroll
    for (int i = 0; i < 4; i++) {
        int ar = wm * 64 + i * 16 + aRowL;
        aRowOff[i] = ar * 128; aXor[i] = (ar & 7) << 4;
    }
    uint32_t bRowOff[2], bXor[2];
    #pragma unroll
    for (int p = 0; p < 2; p++) {
        int br = wn * 32 + p * 16 + bRowL;
        bRowOff[p] = br * 128; bXor[p] = (br & 7) << 4;
    }

    float acc[4][4][4] = {};
    loadChunk(0, 0);
    loadChunk(1, 1);

    for (int c = 0; c < 8; c++) {
        if (c < 7) cp_wait<1>(); else cp_wait<0>();
        __syncthreads();
        if (c + 2 < 8) loadChunk(c + 2, (c + 2) % 3);

        const uint32_t stage = sb + (c % 3) * ST1;
        const uint32_t aPl = stage, bPl = stage + 16384;

        #pragma unroll
        for (int s = 0; s < 4; s++) {
            uint32_t ah[4][4], bh[2][4];
            uint32_t aCol = (uint32_t)(s * 32 + aKb * 16);
            uint32_t bCol = (uint32_t)(s * 32 + bKb * 16);
            #pragma unroll
            for (int i = 0; i < 4; i++)
                ldm_x4(ah[i], aPl + aRowOff[i] + (aCol ^ aXor[i]));
            #pragma unroll
            for (int p = 0; p < 2; p++)
                ldm_x4(bh[p], bPl + bRowOff[p] + (bCol ^ bXor[p]));
            #pragma unroll
            for (int i = 0; i < 4; i++)
                #pragma unroll
                for (int j = 0; j < 4; j++)
                    mma16816(acc[i][j], ah[i], &bh[j >> 1][(j & 1) * 2]);
        }
    }
    __syncthreads();   // protect epilogue smem reuse against last chunk reads

    const int rlane = lane >> 2;
    const int clane = (lane & 3) * 2;
    float* sE = (float*)smem;                 // [128][129]

    #pragma unroll
    for (int i = 0; i < 4; i++) {
        int rl0 = wm * 64 + i * 16 + rlane;
        #pragma unroll
        for (int j = 0; j < 4; j++) {
            int cl = wn * 32 + j * 8 + clane;
            int col = colBase + cl;
            float o0 = bias2[col], o1 = bias2[col + 1];
            #pragma unroll
            for (int h = 0; h < 2; h++) {
                int rl = rl0 + h * 8;
                float v0 = acc[i][j][h * 2 + 0] + o0;
                float v1 = acc[i][j][h * 2 + 1] + o1;
                v0 = v0 > 0.f ? v0 : expm1f(v0);
                v1 = v1 > 0.f ? v1 : expm1f(v1);
                sE[rl * 129 + cl] = v0;
                sE[rl * 129 + cl + 1] = v1;
            }
        }
    }

    // fused pool: partial logits = sE(128x128) @ pool_w[colBase:colBase+128, 0:16]
    float* sPw = sE + 128 * 129;              // [128][16] = 8 KB
    __syncthreads();
    #pragma unroll
    for (int jj = 0; jj < 8; jj++) {
        int idx = tid * 8 + jj;
        int k = idx >> 4, cch = idx & 15;
        sPw[k * 16 + cch] = poolw[(size_t)(colBase + k) * CC + cch];
    }
    __syncthreads();
    int r = tid & 127;
    int c0 = (tid >> 7) * 8;
    float a8[8] = {};
    #pragma unroll 4
    for (int k = 0; k < 128; k++) {
        float zv = sE[r * 129 + k];
        #pragma unroll
        for (int c8 = 0; c8 < 8; c8++) a8[c8] += zv * sPw[k * 16 + c0 + c8];
    }
    float* dst = g_logits + (size_t)(rowBase + r) * CC + c0;
    #pragma unroll
    for (int c8 = 0; c8 < 8; c8++) atomicAdd(dst + c8, a8[c8]);
}

// ---------------- per-batch losses (softmax fused; self-cleaning tail) ----------------
__global__ __launch_bounds__(256) void loss_kernel(const int* __restrict__ ei,
                                                   const float* __restrict__ pb,
                                                   float* __restrict__ out) {
    __shared__ float ssh[NN * CC];
    __shared__ float dsh[NN];
    __shared__ float wsh[CC], csh[CC], pbs[CC];
    __shared__ float sAcc[4];
    int b = blockIdx.x, t = threadIdx.x;
    int lane = t & 31;

    for (int i = t; i < NN * CC; i += 256) ssh[i] = g_logits[b * NN * CC + i];
    for (int i = t; i < NN; i += 256) dsh[i] = (float)g_deg[b * NN + i];
    if (t < CC) { wsh[t] = 0.f; csh[t] = 0.f; pbs[t] = pb[t]; }
    if (t < 4) sAcc[t] = 0.f;
    __syncthreads();

    // self-cleaning for next call / graph replay
    for (int i = t; i < NN; i += 256) {
        int nb = b * NN + i;
        g_cnt[nb] = 0; g_deg[nb] = 0;
        float4 z = make_float4(0.f, 0.f, 0.f, 0.f);
        float4* lg = (float4*)(g_logits + (size_t)nb * CC);
        lg[0] = z; lg[1] = z; lg[2] = z; lg[3] = z;
    }

    for (int r = t; r < NN; r += 256) {
        float* row = ssh + r * CC;
        float l[CC];
        float mx = -INFINITY;
        #pragma unroll
        for (int c = 0; c < CC; c++) { l[c] = row[c] + pbs[c]; mx = fmaxf(mx, l[c]); }
        float sum = 0.f;
        #pragma unroll
        for (int c = 0; c < CC; c++) { l[c] = expf(l[c] - mx); sum += l[c]; }
        float inv = 1.f / sum;
        #pragma unroll
        for (int c = 0; c < CC; c++) row[c] = l[c] * inv;
    }
    __syncthreads();

    float wp[CC] = {}, cp[CC] = {};
    float td = 0.f;
    for (int n = t; n < NN; n += 256) {
        float d = dsh[n];
        td += d;
        #pragma unroll
        for (int c = 0; c < CC; c++) {
            float sv = ssh[n * CC + c];
            wp[c] += sv * d;
            cp[c] += sv;
        }
    }
    td = warpSum(td);
    #pragma unroll
    for (int c = 0; c < CC; c++) { wp[c] = warpSum(wp[c]); cp[c] = warpSum(cp[c]); }
    if (lane == 0) {
        atomicAdd(&sAcc[0], td);
        #pragma unroll
        for (int c = 0; c < CC; c++) { atomicAdd(&wsh[c], wp[c]); atomicAdd(&csh[c], cp[c]); }
    }

    int cc = t >> 4, kk = t & 15;
    float ssv = 0.f;
    for (int n = 0; n < NN; n++) ssv += ssh[n * CC + cc] * ssh[n * CC + kk];
    float s2 = warpSum(ssv * ssv);
    if (lane == 0) atomicAdd(&sAcc[2], s2);

    const int* srcp = ei;
    const int* dstp = ei + ETOT;
    float et = 0.f;
    for (int e = b * EB + t; e < (b + 1) * EB; e += 256) {
        int sl = srcp[e] - b * NN;
        int dl = dstp[e] - b * NN;
        float d2 = 0.f;
        #pragma unroll
        for (int c = 0; c < CC; c++) d2 += ssh[sl * CC + c] * ssh[dl * CC + c];
        et += d2;
    }
    et = warpSum(et);
    if (lane == 0) atomicAdd(&sAcc[1], et);
    __syncthreads();

    float fro = sqrtf(sAcc[2]);
    float dd = ssv / fro - ((cc == kk) ? 0.25f : 0.f);
    float dsq = warpSum(dd * dd);
    if (lane == 0) atomicAdd(&sAcc[3], dsq);
    __syncthreads();

    if (t == 0) {
        float m = sAcc[0] * 0.5f;
        float wsq = 0.f, cs2 = 0.f;
        #pragma unroll
        for (int c = 0; c < CC; c++) { wsq += wsh[c] * wsh[c]; cs2 += csh[c] * csh[c]; }
        float trace = sAcc[1] - wsq / (2.f * m);
        float spec = -trace / (2.f * m);
        float ortho = sqrtf(sAcc[3]);
        float cluster = sqrtf(cs2) / (float)NN * 4.f - 1.f;
        atomicAdd(out, (spec + ortho + cluster) * (1.f / (float)BB));
    }
}

// ---------------- launch ----------------
extern "C" void kernel_launch(void* const* d_in, const int* in_sizes, int n_in,
                              void* d_out, int out_size) {
    const int*   x      = (const int*)d_in[0];
    const int*   ei     = (const int*)d_in[1];
    const float* emb    = (const float*)d_in[3];
    const float* w1     = (const float*)d_in[4];
    const float* b1     = (const float*)d_in[5];
    const float* bn_g   = (const float*)d_in[6];
    const float* bn_b   = (const float*)d_in[7];
    const float* bn_m   = (const float*)d_in[8];
    const float* bn_v   = (const float*)d_in[9];
    const float* w2     = (const float*)d_in[10];
    const float* b2     = (const float*)d_in[11];
    const float* pool_w = (const float*)d_in[12];
    const float* pool_b = (const float*)d_in[13];
    float* out = (float*)d_out;

    cudaFuncSetAttribute(gemm0_kernel, cudaFuncAttributeMaxDynamicSharedMemorySize, SM0);
    cudaFuncSetAttribute(gemm1_kernel, cudaFuncAttributeMaxDynamicSharedMemorySize, SM1);

    prep_kernel<<<(VOCAB * HD / 2 + 255) / 256, 256>>>(ei, emb, w1, w2, b1,
                                                       bn_g, bn_b, bn_m, bn_v, out);
    z0_kernel<<<MROWS / 4, 256>>>(x);

    dim3 g0(HD / 64, MROWS / 128);    // (8, 256)
    gemm0_kernel<<<g0, 256, SM0>>>();
    dim3 g1(HD / 128, MROWS / 128);   // (4, 256)
    gemm1_kernel<<<g1, 256, SM1>>>(b2, pool_w);

    loss_kernel<<<BB, 256>>>(ei, pool_b, out);
}